// round 13
// baseline (speedup 1.0000x reference)
#include <cuda_runtime.h>
#include <cuda_bf16.h>
#include <math.h>

#define SEQ   512
#define BATCH 64
#define DIM   512
#define G4    2048
#define NT    8
#define HD    64
#define TL    64
#define NACT  72
#define MROWS (SEQ*BATCH)

__device__ float g_xg [(size_t)MROWS*G4];    // TRANSPOSED: [s][n=2048][b=64]
__device__ float g_val[(size_t)MROWS*DIM];
__device__ float g_act[(size_t)MROWS*NACT];
__device__ float g_ro [(size_t)MROWS*DIM];
__device__ __nv_bfloat16 g_hhh[(size_t)(SEQ+1)*BATCH*DIM];  // h hi history [s][b][k]
__device__ __nv_bfloat16 g_hhl[(size_t)(SEQ+1)*BATCH*DIM];  // h lo history
__device__ unsigned g_bar;

__device__ __forceinline__ float sigf(float x){ return 1.f/(1.f+__expf(-x)); }

__device__ __forceinline__ void cp16(void* dst_smem, const void* src){
  unsigned d = (unsigned)__cvta_generic_to_shared(dst_smem);
  asm volatile("cp.async.ca.shared.global [%0], [%1], 16;\n" :: "r"(d), "l"(src));
}
#define CP_COMMIT() asm volatile("cp.async.commit_group;\n" ::: "memory")
#define CP_WAIT0()  asm volatile("cp.async.wait_group 0;\n" ::: "memory")

__global__ void init_kernel(){
  unsigned i = blockIdx.x*256u + threadIdx.x;
  if (i==0) g_bar = 0u;
  if (i < DIM*BATCH){
    g_hhh[i] = __float2bfloat16(0.f);
    g_hhl[i] = __float2bfloat16(0.f);
  }
}

// ================= bf16-split tensor GEMM (validated) ========================
#define GSTRIDE 24

__device__ __forceinline__ void cvt_store(__nv_bfloat16* Hp, __nv_bfloat16* Lp, float4 v){
  __nv_bfloat16 h0=__float2bfloat16(v.x), h1=__float2bfloat16(v.y);
  __nv_bfloat16 h2=__float2bfloat16(v.z), h3=__float2bfloat16(v.w);
  __nv_bfloat16 l0=__float2bfloat16(v.x-__bfloat162float(h0));
  __nv_bfloat16 l1=__float2bfloat16(v.y-__bfloat162float(h1));
  __nv_bfloat16 l2=__float2bfloat16(v.z-__bfloat162float(h2));
  __nv_bfloat16 l3=__float2bfloat16(v.w-__bfloat162float(h3));
  ((__nv_bfloat162*)Hp)[0] = __nv_bfloat162(h0,h1);
  ((__nv_bfloat162*)Hp)[1] = __nv_bfloat162(h2,h3);
  ((__nv_bfloat162*)Lp)[0] = __nv_bfloat162(l0,l1);
  ((__nv_bfloat162*)Lp)[1] = __nv_bfloat162(l2,l3);
}

#define MMA16816(C, A, B) \
  asm volatile("mma.sync.aligned.m16n8k16.row.col.f32.bf16.bf16.f32 " \
    "{%0,%1,%2,%3}, {%4,%5,%6,%7}, {%8,%9}, {%0,%1,%2,%3};" \
    : "+f"((C)[0]),"+f"((C)[1]),"+f"((C)[2]),"+f"((C)[3]) \
    : "r"((A)[0]),"r"((A)[1]),"r"((A)[2]),"r"((A)[3]), "r"((B)[0]),"r"((B)[1]))

#define LDSM4(R, addr) \
  asm volatile("ldmatrix.sync.aligned.m8n8.x4.shared.b16 {%0,%1,%2,%3}, [%4];" \
    : "=r"((R)[0]),"=r"((R)[1]),"=r"((R)[2]),"=r"((R)[3]) : "r"(addr))

#define LDSM2(R, addr) \
  asm volatile("ldmatrix.sync.aligned.m8n8.x2.shared.b16 {%0,%1}, [%2];" \
    : "=r"((R)[0]),"=r"((R)[1]) : "r"(addr))

// transC=0: C[row][col]; transC=1: C[(row>>6)*N + col][row&63]
__launch_bounds__(256)
__global__ void tgemm_bias(const float* __restrict__ A, const float* __restrict__ W,
                           const float* __restrict__ b1, const float* __restrict__ b2,
                           float* __restrict__ C, int N, int K, int transC)
{
  __shared__ __nv_bfloat16 sm[2][4][128*GSTRIDE];
  const int tid = threadIdx.x;
  const int lane = tid & 31, warp = tid >> 5;
  const int warpM = (warp>>2)*64, warpN = (warp&3)*32;
  const int ctaM = blockIdx.y*128, ctaN = blockIdx.x*128;

  float acc[4][4][4];
#pragma unroll
  for (int mf=0;mf<4;mf++)
#pragma unroll
    for (int nf=0;nf<4;nf++)
#pragma unroll
      for (int i=0;i<4;i++) acc[mf][nf][i]=0.f;

  const float* Abase = A + (size_t)ctaM*K;
  const float* Wbase = W + (size_t)ctaN*K;
  const int r0 = tid>>2, kq = tid&3;
  const int sts_off = r0*GSTRIDE + kq*4;
  const int a_row = lane & 15, a_kh = (lane>>4)*8;
  const int b_row = lane & 7,  b_kh = ((lane>>3)&1)*8;

  unsigned smem_u32[2][4];
#pragma unroll
  for (int bf=0;bf<2;bf++)
#pragma unroll
    for (int q=0;q<4;q++) smem_u32[bf][q] = (unsigned)__cvta_generic_to_shared(sm[bf][q]);

  float4 ra0, ra1, rw0, rw1;
  ra0 = *(const float4*)(Abase + (size_t)r0*K + kq*4);
  ra1 = *(const float4*)(Abase + (size_t)(r0+64)*K + kq*4);
  rw0 = *(const float4*)(Wbase + (size_t)r0*K + kq*4);
  rw1 = *(const float4*)(Wbase + (size_t)(r0+64)*K + kq*4);
  cvt_store(&sm[0][0][sts_off],              &sm[0][1][sts_off],              ra0);
  cvt_store(&sm[0][0][sts_off+64*GSTRIDE],   &sm[0][1][sts_off+64*GSTRIDE],   ra1);
  cvt_store(&sm[0][2][sts_off],              &sm[0][3][sts_off],              rw0);
  cvt_store(&sm[0][2][sts_off+64*GSTRIDE],   &sm[0][3][sts_off+64*GSTRIDE],   rw1);
  __syncthreads();

  const int nchunk = K/16;
  for (int kc = 0; kc < nchunk; kc++){
    const int buf = kc & 1;
    if (kc+1 < nchunk){
      const float* ap = Abase + (kc+1)*16;
      const float* wp = Wbase + (kc+1)*16;
      ra0 = *(const float4*)(ap + (size_t)r0*K + kq*4);
      ra1 = *(const float4*)(ap + (size_t)(r0+64)*K + kq*4);
      rw0 = *(const float4*)(wp + (size_t)r0*K + kq*4);
      rw1 = *(const float4*)(wp + (size_t)(r0+64)*K + kq*4);
    }
    unsigned bh[4][2], bl[4][2];
#pragma unroll
    for (int nf=0;nf<4;nf++){
      unsigned off = (unsigned)((warpN + nf*8 + b_row)*GSTRIDE + b_kh)*2u;
      LDSM2(bh[nf], smem_u32[buf][2] + off);
      LDSM2(bl[nf], smem_u32[buf][3] + off);
    }
#pragma unroll
    for (int mf=0;mf<4;mf++){
      unsigned aoff = (unsigned)((warpM + mf*16 + a_row)*GSTRIDE + a_kh)*2u;
      unsigned ah[4], al[4];
      LDSM4(ah, smem_u32[buf][0] + aoff);
      LDSM4(al, smem_u32[buf][1] + aoff);
#pragma unroll
      for (int nf=0;nf<4;nf++){
        MMA16816(acc[mf][nf], ah, bh[nf]);
        MMA16816(acc[mf][nf], ah, bl[nf]);
        MMA16816(acc[mf][nf], al, bh[nf]);
      }
    }
    if (kc+1 < nchunk){
      const int nb = buf^1;
      cvt_store(&sm[nb][0][sts_off],            &sm[nb][1][sts_off],            ra0);
      cvt_store(&sm[nb][0][sts_off+64*GSTRIDE], &sm[nb][1][sts_off+64*GSTRIDE], ra1);
      cvt_store(&sm[nb][2][sts_off],            &sm[nb][3][sts_off],            rw0);
      cvt_store(&sm[nb][2][sts_off+64*GSTRIDE], &sm[nb][3][sts_off+64*GSTRIDE], rw1);
    }
    __syncthreads();
  }

#pragma unroll
  for (int nf=0;nf<4;nf++){
    int col = ctaN + warpN + nf*8 + (lane&3)*2;
    float bb0 = b1[col]   + (b2 ? b2[col]   : 0.f);
    float bb1 = b1[col+1] + (b2 ? b2[col+1] : 0.f);
#pragma unroll
    for (int mf=0;mf<4;mf++){
      int row = ctaM + warpM + mf*16 + (lane>>2);
      if (!transC){
        *(float2*)(C + (size_t)row*N + col)     = make_float2(acc[mf][nf][0]+bb0, acc[mf][nf][1]+bb1);
        *(float2*)(C + (size_t)(row+8)*N + col) = make_float2(acc[mf][nf][2]+bb0, acc[mf][nf][3]+bb1);
      } else {
        int s0 = row>>6, b0 = row&63;
        int s1 = (row+8)>>6, b1i = (row+8)&63;
        C[((size_t)s0*N + col  )*64 + b0 ] = acc[mf][nf][0]+bb0;
        C[((size_t)s0*N + col+1)*64 + b0 ] = acc[mf][nf][1]+bb1;
        C[((size_t)s1*N + col  )*64 + b1i] = acc[mf][nf][2]+bb0;
        C[((size_t)s1*N + col+1)*64 + b1i] = acc[mf][nf][3]+bb1;
      }
    }
  }
}

// ---------- LSTM v10: 64 CTAs x 512 thr, 8 cols/CTA, red aliases H ----------
#define HST 520
#define HHI 0
#define HLO (64*HST)
#define SWH (128*HST)
#define SWL (160*HST)
#define LS10_SMEM (192*HST*2)

extern __shared__ float ls_smem[];

__launch_bounds__(512, 1)
__global__ void lstm10_kernel(const float* __restrict__ W_hh)
{
  __nv_bfloat16* sb = (__nv_bfloat16*)ls_smem;
  float* red = ls_smem;    // aliases H region (guarded by syncs)

  const int t = threadIdx.x, lane = t&31, w = t>>5;
  const int c0 = blockIdx.x*8;
  const int mw = w&3, kh = w>>2;        // kh 0..3 (128 k each)
  const int fj = t>>6, fb = t&63;       // fj 0..7
  const int a_row = lane & 15, a_kh = (lane>>4)*8;
  const int b_row = lane & 7,  b_kh = ((lane>>3)&1)*8;

  // resident W_hh slice: 32 gate rows (4 gates x 8 cols), hi/lo
  for (int id=t; id<32*512; id+=512){
    int r = id>>9, k = id&511;
    int g = r>>3, jj = r&7;
    float v = W_hh[(size_t)(g*DIM + c0 + jj)*DIM + k];
    __nv_bfloat16 hv = __float2bfloat16(v);
    sb[SWH + r*HST + k] = hv;
    sb[SWL + r*HST + k] = __float2bfloat16(v - __bfloat162float(hv));
  }
  float cstate = 0.f;
  __syncthreads();

  const unsigned sb_u = (unsigned)__cvta_generic_to_shared(sb);

  // hoist hi-W fragments (lo-W stays in SMEM, loaded per step)
  unsigned wfh[8][4][2];
#pragma unroll
  for (int ks=0; ks<8; ks++){
    const int kbase = kh*128 + ks*16;
#pragma unroll
    for (int nf=0;nf<4;nf++){
      unsigned bo = (unsigned)((SWH + (nf*8 + b_row)*HST + kbase + b_kh))*2u;
      LDSM2(wfh[ks][nf], sb_u + bo);
    }
  }

  for (int s=0; s<SEQ; s++){
    const float* xgp = g_xg + ((size_t)s*G4 + (c0+fj))*64 + fb;
    float x0 = xgp[0], x1 = xgp[512*64], x2 = xgp[2*512*64], x3 = xgp[3*512*64];

    // warp-private A tile: 16 batches x 128 k, hi+lo
    {
      const __nv_bfloat16* srcH = g_hhh + (size_t)s*BATCH*DIM;
      const __nv_bfloat16* srcL = g_hhl + (size_t)s*BATCH*DIM;
#pragma unroll
      for (int i=0;i<8;i++){
        int idx = lane + i*32;           // 0..255
        int row = idx>>4, ch = idx&15;
        int soff = (mw*16+row)*HST + kh*128 + ch*8;
        int goff = (mw*16+row)*512 + kh*128 + ch*8;
        cp16(sb + HHI + soff, srcH + goff);
        cp16(sb + HLO + soff, srcL + goff);
      }
      CP_COMMIT();
      CP_WAIT0();
      __syncwarp();
    }

    float acc[4][4];
#pragma unroll
    for (int nf=0;nf<4;nf++)
#pragma unroll
      for (int i=0;i<4;i++) acc[nf][i]=0.f;

#pragma unroll
    for (int ks=0; ks<8; ks++){
      const int kbase = kh*128 + ks*16;
      unsigned ah[4], al[4];
      unsigned aoff = (unsigned)((HHI + (mw*16 + a_row)*HST + kbase + a_kh))*2u;
      unsigned loff = (unsigned)((HLO + (mw*16 + a_row)*HST + kbase + a_kh))*2u;
      LDSM4(ah, sb_u + aoff);
      LDSM4(al, sb_u + loff);
#pragma unroll
      for (int nf=0;nf<4;nf++){
        unsigned wl[2];
        unsigned bo = (unsigned)((SWL + (nf*8 + b_row)*HST + kbase + b_kh))*2u;
        LDSM2(wl, sb_u + bo);
        MMA16816(acc[nf], ah, wfh[ks][nf]);
        MMA16816(acc[nf], ah, wl);
        MMA16816(acc[nf], al, wfh[ks][nf]);
      }
    }
    __syncthreads();   // ALL warps done reading H before red (aliased) writes

#pragma unroll
    for (int nf=0;nf<4;nf++){
      int n0 = nf*8 + (lane&3)*2;
      int b0 = mw*16 + (lane>>2);
      red[(kh*32 + n0  )*68 + b0  ] = acc[nf][0];
      red[(kh*32 + n0+1)*68 + b0  ] = acc[nf][1];
      red[(kh*32 + n0  )*68 + b0+8] = acc[nf][2];
      red[(kh*32 + n0+1)*68 + b0+8] = acc[nf][3];
    }
    __syncthreads();

    {
      float gi=x0, gf=x1, gg2=x2, go=x3;
#pragma unroll
      for (int k2=0;k2<4;k2++){
        gi  += red[(k2*32 +  0 + fj)*68 + fb];
        gf  += red[(k2*32 +  8 + fj)*68 + fb];
        gg2 += red[(k2*32 + 16 + fj)*68 + fb];
        go  += red[(k2*32 + 24 + fj)*68 + fb];
      }
      cstate = sigf(gf)*cstate + sigf(gi)*tanhf(gg2);
      float hv = sigf(go)*tanhf(cstate);
      __nv_bfloat16 hh = __float2bfloat16(hv);
      size_t ho = (size_t)(s+1)*BATCH*DIM + fb*512 + c0 + fj;
      g_hhh[ho] = hh;
      g_hhl[ho] = __float2bfloat16(hv - __bfloat162float(hh));
    }
    __syncthreads();

    if (t==0){
      asm volatile("red.release.gpu.global.add.u32 [%0], %1;" ::
                   "l"(&g_bar), "r"(1u) : "memory");
      unsigned v;
      do {
        asm volatile("ld.acquire.gpu.global.u32 %0, [%1];" : "=r"(v) : "l"(&g_bar));
      } while (v < (unsigned)(s+1)*64u);
    }
    __syncthreads();
  }
}

// actions[s][b][a] = h[s] @ W_act.T + b_act  (N=72); h from hi+lo history
__launch_bounds__(256)
__global__ void actions_kernel(const float* __restrict__ W_act, const float* __restrict__ b_act)
{
  __shared__ float hs[64*65];
  __shared__ float ws[NACT*64];
  const int s = blockIdx.x, t = threadIdx.x;
  const int b = t&63, ag = t>>6;
  const __nv_bfloat16* hb = g_hhh + (size_t)(s+1)*BATCH*DIM;
  const __nv_bfloat16* hl = g_hhl + (size_t)(s+1)*BATCH*DIM;
  float acc[18];
#pragma unroll
  for (int i=0;i<18;i++) acc[i]=0.f;

  for (int j0=0;j0<DIM;j0+=64){
#pragma unroll
    for (int i=0;i<16;i++){
      int idx = t + i*256;
      int bb = idx>>6, jj = idx&63;
      hs[bb*65 + jj] = __bfloat162float(hb[bb*512 + j0 + jj])
                     + __bfloat162float(hl[bb*512 + j0 + jj]);
    }
    for (int i=t;i<NACT*16;i+=256){
      int a = i>>4, jj = i&15;
      *(float4*)&ws[a*64 + jj*4] = *(const float4*)(W_act + (size_t)a*DIM + j0 + jj*4);
    }
    __syncthreads();
#pragma unroll 8
    for (int j=0;j<64;j++){
      float hv = hs[b*65 + j];
#pragma unroll
      for (int ii=0;ii<18;ii++) acc[ii] += hv * ws[(ag*18+ii)*64 + j];
    }
    __syncthreads();
  }
#pragma unroll
  for (int ii=0;ii<18;ii++){
    int a = ag*18+ii;
    g_act[((size_t)s*BATCH + b)*NACT + a] = acc[ii] + b_act[a];
  }
}

// NTM scan with software-pipelined act/val prefetch
__launch_bounds__(64)
__global__ void tape_kernel(float* __restrict__ out)
{
  __shared__ float wpos[TL], rpos[TL], rpr[TL];
  const int bb = blockIdx.x>>3, tp = blockIdx.x&7, c = threadIdx.x;
  float tape[TL];
#pragma unroll
  for (int l=0;l<TL;l++) tape[l]=0.f;
  wpos[c] = (c==0)?1.f:0.f;
  rpos[c] = (c==0)?1.f:0.f;
  __syncthreads();

  float ca[9], cv;
  {
    const float* ap = g_act + (size_t)bb*NACT + tp*9;
#pragma unroll
    for (int i=0;i<9;i++) ca[i] = ap[i];
    cv = g_val[(size_t)bb*DIM + tp*HD + c];
  }

  for (int s=0;s<SEQ;s++){
    float na[9], nv = 0.f;
#pragma unroll
    for (int i=0;i<9;i++) na[i] = 0.f;
    if (s+1 < SEQ){
      const float* np = g_act + ((size_t)(s+1)*BATCH + bb)*NACT + tp*9;
#pragma unroll
      for (int i=0;i<9;i++) na[i] = np[i];
      nv = g_val[((size_t)(s+1)*BATCH + bb)*DIM + tp*HD + c];
    }

    float r0=ca[0], r1=ca[1], r2=ca[2];
    float w0=ca[3], w1=ca[4], w2=ca[5];
    float rw0=sigf(ca[6]), rw1=sigf(ca[7]), rw2=sigf(ca[8]);

    float mr = fmaxf(r0,fmaxf(r1,r2));
    float e0=__expf(r0-mr), e1=__expf(r1-mr), e2=__expf(r2-mr);
    float ir = 1.f/(e0+e1+e2);
    float rd0=e0*ir, rd1=e1*ir, rd2=e2*ir;
    float mw = fmaxf(w0,fmaxf(w1,w2));
    float f0=__expf(w0-mw), f1=__expf(w1-mw), f2=__expf(w2-mw);
    float iw = 1.f/(f0+f1+f2);
    float wd0=f0*iw, wd1=f1*iw, wd2=f2*iw;

    float v = cv;

    float oldv = 0.f;
#pragma unroll
    for (int l=0;l<TL;l++) oldv += tape[l]*wpos[l];

    float nw = wpos[(c+1)&63]*wd0 + wpos[c]*wd1 + wpos[(c+63)&63]*wd2;
    float nr = rpos[(c+1)&63]*rd0 + rpos[c]*rd1 + rpos[(c+63)&63]*rd2;
    rpr[c] = rpos[c]*rw0;
    __syncthreads();

    float upd = v*rw1 - oldv*rw2;
    float ro = 0.f;
#pragma unroll
    for (int l=0;l<TL;l++){
      tape[l] += wpos[l]*upd;
      ro += tape[l]*rpr[l];
    }
    __syncthreads();
    wpos[c]=nw; rpos[c]=nr;
    g_ro[((size_t)s*BATCH + bb)*DIM + tp*HD + c] = ro;
    __syncthreads();

#pragma unroll
    for (int i=0;i<9;i++) ca[i] = na[i];
    cv = nv;
  }
#pragma unroll
  for (int l=0;l<TL;l++)
    out[(size_t)SEQ*BATCH*DIM + ((size_t)l*BATCH + bb)*DIM + tp*HD + c] = tape[l];
}

extern "C" void kernel_launch(void* const* d_in, const int* in_sizes, int n_in,
                              void* d_out, int out_size)
{
  const float* inputs = (const float*)d_in[0];
  const float* W_ih   = (const float*)d_in[1];
  const float* W_hh   = (const float*)d_in[2];
  const float* b_ih   = (const float*)d_in[3];
  const float* b_hh   = (const float*)d_in[4];
  const float* W_act  = (const float*)d_in[5];
  const float* b_act  = (const float*)d_in[6];
  const float* W_val  = (const float*)d_in[7];
  const float* b_val  = (const float*)d_in[8];
  const float* W_out  = (const float*)d_in[9];
  const float* b_out  = (const float*)d_in[10];
  float* out = (float*)d_out;

  float *xg_p, *val_p, *ro_p;
  cudaGetSymbolAddress((void**)&xg_p,  g_xg);
  cudaGetSymbolAddress((void**)&val_p, g_val);
  cudaGetSymbolAddress((void**)&ro_p,  g_ro);

  cudaFuncSetAttribute(lstm10_kernel, cudaFuncAttributeMaxDynamicSharedMemorySize, LS10_SMEM);

  init_kernel<<<128,256>>>();
  tgemm_bias<<<dim3(16,256),256>>>(inputs, W_ih, b_ih, b_hh, xg_p, G4, DIM, 1);
  tgemm_bias<<<dim3(4,256),256>>>(inputs, W_val, b_val, nullptr, val_p, DIM, DIM, 0);
  lstm10_kernel<<<64,512,LS10_SMEM>>>(W_hh);
  actions_kernel<<<SEQ,256>>>(W_act, b_act);
  tape_kernel<<<512,64>>>(out);
  tgemm_bias<<<dim3(4,256),256>>>(ro_p, W_out, b_out, nullptr, out, DIM, DIM, 0);
}

// round 14
// speedup vs baseline: 1.1595x; 1.1595x over previous
#include <cuda_runtime.h>
#include <cuda_bf16.h>
#include <math.h>

#define SEQ   512
#define BATCH 64
#define DIM   512
#define G4    2048
#define NT    8
#define HD    64
#define TL    64
#define NACT  72
#define MROWS (SEQ*BATCH)

__device__ float g_xg [(size_t)MROWS*G4];    // TRANSPOSED: [s][n=2048][b=64]
__device__ float g_val[(size_t)MROWS*DIM];
__device__ float g_act[(size_t)MROWS*NACT];
__device__ float g_ro [(size_t)MROWS*DIM];
__device__ __nv_bfloat16 g_hhh[(size_t)(SEQ+1)*BATCH*DIM];  // h hi history [s][b][k]
__device__ __nv_bfloat16 g_hhl[(size_t)(SEQ+1)*BATCH*DIM];  // h lo history
__device__ unsigned g_bar;

__device__ __forceinline__ float sigf(float x){ return 1.f/(1.f+__expf(-x)); }

__device__ __forceinline__ void cp16(void* dst_smem, const void* src){
  unsigned d = (unsigned)__cvta_generic_to_shared(dst_smem);
  asm volatile("cp.async.ca.shared.global [%0], [%1], 16;\n" :: "r"(d), "l"(src));
}
#define CP_COMMIT() asm volatile("cp.async.commit_group;\n" ::: "memory")
#define CP_WAIT0()  asm volatile("cp.async.wait_group 0;\n" ::: "memory")

__global__ void init_kernel(){
  unsigned i = blockIdx.x*256u + threadIdx.x;
  if (i==0) g_bar = 0u;
  if (i < DIM*BATCH){
    g_hhh[i] = __float2bfloat16(0.f);
    g_hhl[i] = __float2bfloat16(0.f);
  }
}

// ================= bf16-split tensor GEMM (validated) ========================
#define GSTRIDE 24

__device__ __forceinline__ void cvt_store(__nv_bfloat16* Hp, __nv_bfloat16* Lp, float4 v){
  __nv_bfloat16 h0=__float2bfloat16(v.x), h1=__float2bfloat16(v.y);
  __nv_bfloat16 h2=__float2bfloat16(v.z), h3=__float2bfloat16(v.w);
  __nv_bfloat16 l0=__float2bfloat16(v.x-__bfloat162float(h0));
  __nv_bfloat16 l1=__float2bfloat16(v.y-__bfloat162float(h1));
  __nv_bfloat16 l2=__float2bfloat16(v.z-__bfloat162float(h2));
  __nv_bfloat16 l3=__float2bfloat16(v.w-__bfloat162float(h3));
  ((__nv_bfloat162*)Hp)[0] = __nv_bfloat162(h0,h1);
  ((__nv_bfloat162*)Hp)[1] = __nv_bfloat162(h2,h3);
  ((__nv_bfloat162*)Lp)[0] = __nv_bfloat162(l0,l1);
  ((__nv_bfloat162*)Lp)[1] = __nv_bfloat162(l2,l3);
}

#define MMA16816(C, A, B) \
  asm volatile("mma.sync.aligned.m16n8k16.row.col.f32.bf16.bf16.f32 " \
    "{%0,%1,%2,%3}, {%4,%5,%6,%7}, {%8,%9}, {%0,%1,%2,%3};" \
    : "+f"((C)[0]),"+f"((C)[1]),"+f"((C)[2]),"+f"((C)[3]) \
    : "r"((A)[0]),"r"((A)[1]),"r"((A)[2]),"r"((A)[3]), "r"((B)[0]),"r"((B)[1]))

#define LDSM4(R, addr) \
  asm volatile("ldmatrix.sync.aligned.m8n8.x4.shared.b16 {%0,%1,%2,%3}, [%4];" \
    : "=r"((R)[0]),"=r"((R)[1]),"=r"((R)[2]),"=r"((R)[3]) : "r"(addr))

#define LDSM2(R, addr) \
  asm volatile("ldmatrix.sync.aligned.m8n8.x2.shared.b16 {%0,%1}, [%2];" \
    : "=r"((R)[0]),"=r"((R)[1]) : "r"(addr))

// transC=0: C[row][col]; transC=1: C[(row>>6)*N + col][row&63]
__launch_bounds__(256)
__global__ void tgemm_bias(const float* __restrict__ A, const float* __restrict__ W,
                           const float* __restrict__ b1, const float* __restrict__ b2,
                           float* __restrict__ C, int N, int K, int transC)
{
  __shared__ __nv_bfloat16 sm[2][4][128*GSTRIDE];
  const int tid = threadIdx.x;
  const int lane = tid & 31, warp = tid >> 5;
  const int warpM = (warp>>2)*64, warpN = (warp&3)*32;
  const int ctaM = blockIdx.y*128, ctaN = blockIdx.x*128;

  float acc[4][4][4];
#pragma unroll
  for (int mf=0;mf<4;mf++)
#pragma unroll
    for (int nf=0;nf<4;nf++)
#pragma unroll
      for (int i=0;i<4;i++) acc[mf][nf][i]=0.f;

  const float* Abase = A + (size_t)ctaM*K;
  const float* Wbase = W + (size_t)ctaN*K;
  const int r0 = tid>>2, kq = tid&3;
  const int sts_off = r0*GSTRIDE + kq*4;
  const int a_row = lane & 15, a_kh = (lane>>4)*8;
  const int b_row = lane & 7,  b_kh = ((lane>>3)&1)*8;

  unsigned smem_u32[2][4];
#pragma unroll
  for (int bf=0;bf<2;bf++)
#pragma unroll
    for (int q=0;q<4;q++) smem_u32[bf][q] = (unsigned)__cvta_generic_to_shared(sm[bf][q]);

  float4 ra0, ra1, rw0, rw1;
  ra0 = *(const float4*)(Abase + (size_t)r0*K + kq*4);
  ra1 = *(const float4*)(Abase + (size_t)(r0+64)*K + kq*4);
  rw0 = *(const float4*)(Wbase + (size_t)r0*K + kq*4);
  rw1 = *(const float4*)(Wbase + (size_t)(r0+64)*K + kq*4);
  cvt_store(&sm[0][0][sts_off],              &sm[0][1][sts_off],              ra0);
  cvt_store(&sm[0][0][sts_off+64*GSTRIDE],   &sm[0][1][sts_off+64*GSTRIDE],   ra1);
  cvt_store(&sm[0][2][sts_off],              &sm[0][3][sts_off],              rw0);
  cvt_store(&sm[0][2][sts_off+64*GSTRIDE],   &sm[0][3][sts_off+64*GSTRIDE],   rw1);
  __syncthreads();

  const int nchunk = K/16;
  for (int kc = 0; kc < nchunk; kc++){
    const int buf = kc & 1;
    if (kc+1 < nchunk){
      const float* ap = Abase + (kc+1)*16;
      const float* wp = Wbase + (kc+1)*16;
      ra0 = *(const float4*)(ap + (size_t)r0*K + kq*4);
      ra1 = *(const float4*)(ap + (size_t)(r0+64)*K + kq*4);
      rw0 = *(const float4*)(wp + (size_t)r0*K + kq*4);
      rw1 = *(const float4*)(wp + (size_t)(r0+64)*K + kq*4);
    }
    unsigned bh[4][2], bl[4][2];
#pragma unroll
    for (int nf=0;nf<4;nf++){
      unsigned off = (unsigned)((warpN + nf*8 + b_row)*GSTRIDE + b_kh)*2u;
      LDSM2(bh[nf], smem_u32[buf][2] + off);
      LDSM2(bl[nf], smem_u32[buf][3] + off);
    }
#pragma unroll
    for (int mf=0;mf<4;mf++){
      unsigned aoff = (unsigned)((warpM + mf*16 + a_row)*GSTRIDE + a_kh)*2u;
      unsigned ah[4], al[4];
      LDSM4(ah, smem_u32[buf][0] + aoff);
      LDSM4(al, smem_u32[buf][1] + aoff);
#pragma unroll
      for (int nf=0;nf<4;nf++){
        MMA16816(acc[mf][nf], ah, bh[nf]);
        MMA16816(acc[mf][nf], ah, bl[nf]);
        MMA16816(acc[mf][nf], al, bh[nf]);
      }
    }
    if (kc+1 < nchunk){
      const int nb = buf^1;
      cvt_store(&sm[nb][0][sts_off],            &sm[nb][1][sts_off],            ra0);
      cvt_store(&sm[nb][0][sts_off+64*GSTRIDE], &sm[nb][1][sts_off+64*GSTRIDE], ra1);
      cvt_store(&sm[nb][2][sts_off],            &sm[nb][3][sts_off],            rw0);
      cvt_store(&sm[nb][2][sts_off+64*GSTRIDE], &sm[nb][3][sts_off+64*GSTRIDE], rw1);
    }
    __syncthreads();
  }

#pragma unroll
  for (int nf=0;nf<4;nf++){
    int col = ctaN + warpN + nf*8 + (lane&3)*2;
    float bb0 = b1[col]   + (b2 ? b2[col]   : 0.f);
    float bb1 = b1[col+1] + (b2 ? b2[col+1] : 0.f);
#pragma unroll
    for (int mf=0;mf<4;mf++){
      int row = ctaM + warpM + mf*16 + (lane>>2);
      if (!transC){
        *(float2*)(C + (size_t)row*N + col)     = make_float2(acc[mf][nf][0]+bb0, acc[mf][nf][1]+bb1);
        *(float2*)(C + (size_t)(row+8)*N + col) = make_float2(acc[mf][nf][2]+bb0, acc[mf][nf][3]+bb1);
      } else {
        int s0 = row>>6, b0 = row&63;
        int s1 = (row+8)>>6, b1i = (row+8)&63;
        C[((size_t)s0*N + col  )*64 + b0 ] = acc[mf][nf][0]+bb0;
        C[((size_t)s0*N + col+1)*64 + b0 ] = acc[mf][nf][1]+bb1;
        C[((size_t)s1*N + col  )*64 + b1i] = acc[mf][nf][2]+bb0;
        C[((size_t)s1*N + col+1)*64 + b1i] = acc[mf][nf][3]+bb1;
      }
    }
  }
}

// ---------- LSTM v9 (round-12 champion): 128 CTAs x 256 thr ------------------
#define HST 520
#define WHI 0
#define WLO (16*HST)
#define HHI (32*HST)
#define HLO (96*HST)
#define REDOFF 41600
#define LS9_SMEM (160*HST*2 + 2*16*68*4)

extern __shared__ float ls_smem[];

__launch_bounds__(256, 1)
__global__ void lstm9_kernel(const float* __restrict__ W_hh)
{
  __nv_bfloat16* sb = (__nv_bfloat16*)ls_smem;
  float* red = ls_smem + REDOFF;

  const int t = threadIdx.x, lane = t&31, w = t>>5;
  const int c0 = blockIdx.x*4;
  const int mw = w&3, kh = w>>2;
  const int fj = t>>6, fb = t&63;
  const int a_row = lane & 15, a_kh = (lane>>4)*8;
  const int b_row = lane & 7,  b_kh = ((lane>>3)&1)*8;

  for (int id=t; id<16*512; id+=256){
    int row16 = id>>9, k = id&511;
    int gg = row16>>2, jj = row16&3;
    float v = W_hh[(size_t)(gg*DIM + c0 + jj)*DIM + k];
    __nv_bfloat16 hv = __float2bfloat16(v);
    sb[WHI + row16*HST + k] = hv;
    sb[WLO + row16*HST + k] = __float2bfloat16(v - __bfloat162float(hv));
  }
  float cstate = 0.f;
  __syncthreads();

  const unsigned sb_u = (unsigned)__cvta_generic_to_shared(sb);

  // hoist W fragments into registers (loop-invariant across all steps)
  unsigned wfh[16][2][2], wfl[16][2][2];
#pragma unroll
  for (int ks=0; ks<16; ks++){
    const int kbase = kh*256 + ks*16;
#pragma unroll
    for (int nf=0;nf<2;nf++){
      unsigned bo = (unsigned)((nf*8 + b_row)*HST + kbase + b_kh)*2u;
      LDSM2(wfh[ks][nf], sb_u + (unsigned)(WHI*2) + bo);
      LDSM2(wfl[ks][nf], sb_u + (unsigned)(WLO*2) + bo);
    }
  }

  for (int s=0; s<SEQ; s++){
    // coalesced xg prefetch: layout [s][n][b]
    const float* xgp = g_xg + ((size_t)s*G4 + (c0+fj))*64 + fb;
    float x0 = xgp[0], x1 = xgp[512*64], x2 = xgp[2*512*64], x3 = xgp[3*512*64];

    // warp-private A tile: 16 batches x 256 k, hi+lo, from history planes
    {
      const __nv_bfloat16* srcH = g_hhh + (size_t)s*BATCH*DIM;
      const __nv_bfloat16* srcL = g_hhl + (size_t)s*BATCH*DIM;
#pragma unroll
      for (int i=0;i<16;i++){
        int idx = lane + i*32;
        int row = idx>>5, ch = idx&31;
        int soff = (mw*16+row)*HST + kh*256 + ch*8;
        int goff = (mw*16+row)*512 + kh*256 + ch*8;
        cp16(sb + HHI + soff, srcH + goff);
        cp16(sb + HLO + soff, srcL + goff);
      }
      CP_COMMIT();
      CP_WAIT0();
      __syncwarp();
    }

    float acc[2][4];
#pragma unroll
    for (int nf=0;nf<2;nf++)
#pragma unroll
      for (int i=0;i<4;i++) acc[nf][i]=0.f;

#pragma unroll
    for (int ks=0; ks<16; ks++){
      const int kbase = kh*256 + ks*16;
      unsigned ah[4], al[4];
      unsigned aoff = (unsigned)((HHI) + (mw*16 + a_row)*HST + kbase + a_kh)*2u;
      unsigned loff = (unsigned)((HLO) + (mw*16 + a_row)*HST + kbase + a_kh)*2u;
      LDSM4(ah, sb_u + aoff);
      LDSM4(al, sb_u + loff);
#pragma unroll
      for (int nf=0;nf<2;nf++){
        MMA16816(acc[nf], ah, wfh[ks][nf]);
        MMA16816(acc[nf], ah, wfl[ks][nf]);
        MMA16816(acc[nf], al, wfh[ks][nf]);
      }
    }

#pragma unroll
    for (int nf=0;nf<2;nf++){
      int n0 = nf*8 + (lane&3)*2;
      int b0 = mw*16 + (lane>>2);
      red[(kh*16 + n0  )*68 + b0  ] = acc[nf][0];
      red[(kh*16 + n0+1)*68 + b0  ] = acc[nf][1];
      red[(kh*16 + n0  )*68 + b0+8] = acc[nf][2];
      red[(kh*16 + n0+1)*68 + b0+8] = acc[nf][3];
    }
    __syncthreads();

    {
      float gi=x0, gf=x1, gg2=x2, go=x3;
#pragma unroll
      for (int k2=0;k2<2;k2++){
        gi  += red[(k2*16 +  0 + fj)*68 + fb];
        gf  += red[(k2*16 +  4 + fj)*68 + fb];
        gg2 += red[(k2*16 +  8 + fj)*68 + fb];
        go  += red[(k2*16 + 12 + fj)*68 + fb];
      }
      cstate = sigf(gf)*cstate + sigf(gi)*tanhf(gg2);
      float hv = sigf(go)*tanhf(cstate);
      __nv_bfloat16 hh = __float2bfloat16(hv);
      size_t ho = (size_t)(s+1)*BATCH*DIM + fb*512 + c0 + fj;
      g_hhh[ho] = hh;
      g_hhl[ho] = __float2bfloat16(hv - __bfloat162float(hh));
    }
    __syncthreads();

    // grid barrier: release-arrive + acquire-poll
    if (t==0){
      asm volatile("red.release.gpu.global.add.u32 [%0], %1;" ::
                   "l"(&g_bar), "r"(1u) : "memory");
      unsigned v;
      do {
        asm volatile("ld.acquire.gpu.global.u32 %0, [%1];" : "=r"(v) : "l"(&g_bar));
      } while (v < (unsigned)(s+1)*128u);
    }
    __syncthreads();
  }
}

// actions[s][b][a] = h[s] @ W_act.T + b_act  (N=72); h from hi+lo history
__launch_bounds__(256)
__global__ void actions_kernel(const float* __restrict__ W_act, const float* __restrict__ b_act)
{
  __shared__ float hs[64*65];
  __shared__ float ws[NACT*64];
  const int s = blockIdx.x, t = threadIdx.x;
  const int b = t&63, ag = t>>6;
  const __nv_bfloat16* hb = g_hhh + (size_t)(s+1)*BATCH*DIM;
  const __nv_bfloat16* hl = g_hhl + (size_t)(s+1)*BATCH*DIM;
  float acc[18];
#pragma unroll
  for (int i=0;i<18;i++) acc[i]=0.f;

  for (int j0=0;j0<DIM;j0+=64){
#pragma unroll
    for (int i=0;i<16;i++){
      int idx = t + i*256;
      int bb = idx>>6, jj = idx&63;
      hs[bb*65 + jj] = __bfloat162float(hb[bb*512 + j0 + jj])
                     + __bfloat162float(hl[bb*512 + j0 + jj]);
    }
    for (int i=t;i<NACT*16;i+=256){
      int a = i>>4, jj = i&15;
      *(float4*)&ws[a*64 + jj*4] = *(const float4*)(W_act + (size_t)a*DIM + j0 + jj*4);
    }
    __syncthreads();
#pragma unroll 8
    for (int j=0;j<64;j++){
      float hv = hs[b*65 + j];
#pragma unroll
      for (int ii=0;ii<18;ii++) acc[ii] += hv * ws[(ag*18+ii)*64 + j];
    }
    __syncthreads();
  }
#pragma unroll
  for (int ii=0;ii<18;ii++){
    int a = ag*18+ii;
    g_act[((size_t)s*BATCH + b)*NACT + a] = acc[ii] + b_act[a];
  }
}

// NTM scan with software-pipelined act/val prefetch (round-13 win)
__launch_bounds__(64)
__global__ void tape_kernel(float* __restrict__ out)
{
  __shared__ float wpos[TL], rpos[TL], rpr[TL];
  const int bb = blockIdx.x>>3, tp = blockIdx.x&7, c = threadIdx.x;
  float tape[TL];
#pragma unroll
  for (int l=0;l<TL;l++) tape[l]=0.f;
  wpos[c] = (c==0)?1.f:0.f;
  rpos[c] = (c==0)?1.f:0.f;
  __syncthreads();

  float ca[9], cv;
  {
    const float* ap = g_act + (size_t)bb*NACT + tp*9;
#pragma unroll
    for (int i=0;i<9;i++) ca[i] = ap[i];
    cv = g_val[(size_t)bb*DIM + tp*HD + c];
  }

  for (int s=0;s<SEQ;s++){
    float na[9], nv = 0.f;
#pragma unroll
    for (int i=0;i<9;i++) na[i] = 0.f;
    if (s+1 < SEQ){
      const float* np = g_act + ((size_t)(s+1)*BATCH + bb)*NACT + tp*9;
#pragma unroll
      for (int i=0;i<9;i++) na[i] = np[i];
      nv = g_val[((size_t)(s+1)*BATCH + bb)*DIM + tp*HD + c];
    }

    float r0=ca[0], r1=ca[1], r2=ca[2];
    float w0=ca[3], w1=ca[4], w2=ca[5];
    float rw0=sigf(ca[6]), rw1=sigf(ca[7]), rw2=sigf(ca[8]);

    float mr = fmaxf(r0,fmaxf(r1,r2));
    float e0=__expf(r0-mr), e1=__expf(r1-mr), e2=__expf(r2-mr);
    float ir = 1.f/(e0+e1+e2);
    float rd0=e0*ir, rd1=e1*ir, rd2=e2*ir;
    float mw = fmaxf(w0,fmaxf(w1,w2));
    float f0=__expf(w0-mw), f1=__expf(w1-mw), f2=__expf(w2-mw);
    float iw = 1.f/(f0+f1+f2);
    float wd0=f0*iw, wd1=f1*iw, wd2=f2*iw;

    float v = cv;

    float oldv = 0.f;
#pragma unroll
    for (int l=0;l<TL;l++) oldv += tape[l]*wpos[l];

    float nw = wpos[(c+1)&63]*wd0 + wpos[c]*wd1 + wpos[(c+63)&63]*wd2;
    float nr = rpos[(c+1)&63]*rd0 + rpos[c]*rd1 + rpos[(c+63)&63]*rd2;
    rpr[c] = rpos[c]*rw0;
    __syncthreads();

    float upd = v*rw1 - oldv*rw2;
    float ro = 0.f;
#pragma unroll
    for (int l=0;l<TL;l++){
      tape[l] += wpos[l]*upd;
      ro += tape[l]*rpr[l];
    }
    __syncthreads();
    wpos[c]=nw; rpos[c]=nr;
    g_ro[((size_t)s*BATCH + bb)*DIM + tp*HD + c] = ro;
    __syncthreads();

#pragma unroll
    for (int i=0;i<9;i++) ca[i] = na[i];
    cv = nv;
  }
#pragma unroll
  for (int l=0;l<TL;l++)
    out[(size_t)SEQ*BATCH*DIM + ((size_t)l*BATCH + bb)*DIM + tp*HD + c] = tape[l];
}

extern "C" void kernel_launch(void* const* d_in, const int* in_sizes, int n_in,
                              void* d_out, int out_size)
{
  const float* inputs = (const float*)d_in[0];
  const float* W_ih   = (const float*)d_in[1];
  const float* W_hh   = (const float*)d_in[2];
  const float* b_ih   = (const float*)d_in[3];
  const float* b_hh   = (const float*)d_in[4];
  const float* W_act  = (const float*)d_in[5];
  const float* b_act  = (const float*)d_in[6];
  const float* W_val  = (const float*)d_in[7];
  const float* b_val  = (const float*)d_in[8];
  const float* W_out  = (const float*)d_in[9];
  const float* b_out  = (const float*)d_in[10];
  float* out = (float*)d_out;

  float *xg_p, *val_p, *ro_p;
  cudaGetSymbolAddress((void**)&xg_p,  g_xg);
  cudaGetSymbolAddress((void**)&val_p, g_val);
  cudaGetSymbolAddress((void**)&ro_p,  g_ro);

  cudaFuncSetAttribute(lstm9_kernel, cudaFuncAttributeMaxDynamicSharedMemorySize, LS9_SMEM);

  init_kernel<<<128,256>>>();
  tgemm_bias<<<dim3(16,256),256>>>(inputs, W_ih, b_ih, b_hh, xg_p, G4, DIM, 1);
  tgemm_bias<<<dim3(4,256),256>>>(inputs, W_val, b_val, nullptr, val_p, DIM, DIM, 0);
  lstm9_kernel<<<128,256,LS9_SMEM>>>(W_hh);
  actions_kernel<<<SEQ,256>>>(W_act, b_act);
  tape_kernel<<<512,64>>>(out);
  tgemm_bias<<<dim3(4,256),256>>>(ro_p, W_out, b_out, nullptr, out, DIM, DIM, 0);
}